// round 15
// baseline (speedup 1.0000x reference)
#include <cuda_runtime.h>
#include <cuda_bf16.h>
#include <stdint.h>

#define BATCH 128
#define TFRM 80
#define DECL 30
#define DSTEPS 29
#define NSTEP (TFRM + DSTEPS)   // 109
#define EDIM 512
#define G4 2048
#define FEATD 4096
#define VOC 6000
#define PB 40             // bf16 smem pitch (bf16 elems)
#define SMPF 36           // f32 gate-staging pitch
#define BU (BATCH * 1024) // one h12 buffer (elems)
#define NFCH 4            // feat GEMM chunks (20 timesteps each)

// ---------------- scratch (static device globals; no allocation) ----------------
__device__ float g_X1pre[TFRM * BATCH * G4];
__device__ float g_Wx2[DSTEPS * BATCH * G4];
__device__ float g_bias1[G4];
__device__ float g_bias2[G4];
__device__ float g_c1[BATCH * EDIM];
__device__ float g_c2[BATCH * EDIM];
__device__ float g_logits[DSTEPS * BATCH * VOC];
__device__ int   g_labels[DSTEPS * BATCH];
__device__ float g_rowloss[DSTEPS * BATCH];
// bf16 staging
__device__ __nv_bfloat16 g_h12b[4 * BU];              // 4-deep ping-pong [h1 | h2]
__device__ __nv_bfloat16 g_W2catb[G4 * 1024];         // [w_ih2[:,E:2E] ; w_hh2] bf16
__device__ __nv_bfloat16 g_whh1b[G4 * EDIM];          // w_hh1 bf16
__device__ __nv_bfloat16 g_featb[BATCH * TFRM * FEATD];
__device__ __nv_bfloat16 g_capb[BATCH * DECL * EDIM];
__device__ __nv_bfloat16 g_wih1b[G4 * FEATD];
__device__ __nv_bfloat16 g_wih2b[G4 * EDIM];          // packed first-512 cols
__device__ __nv_bfloat16 g_woutb[VOC * EDIM];
__device__ __nv_bfloat16 g_H2b[DSTEPS * BATCH * EDIM];

__device__ __forceinline__ float sigmoidf_(float x) {
    return 1.0f / (1.0f + expf(-x));
}

__device__ __forceinline__ void mma_bf16(float* d, const uint32_t* a, const uint32_t* b) {
    asm volatile(
        "mma.sync.aligned.m16n8k16.row.col.f32.bf16.bf16.f32 "
        "{%0,%1,%2,%3}, {%4,%5,%6,%7}, {%8,%9}, {%0,%1,%2,%3};"
        : "+f"(d[0]), "+f"(d[1]), "+f"(d[2]), "+f"(d[3])
        : "r"(a[0]), "r"(a[1]), "r"(a[2]), "r"(a[3]), "r"(b[0]), "r"(b[1]));
}

__device__ __forceinline__ void ldsm4(uint32_t* r, uint32_t addr) {
    asm volatile("ldmatrix.sync.aligned.m8n8.x4.shared.b16 {%0,%1,%2,%3}, [%4];"
                 : "=r"(r[0]), "=r"(r[1]), "=r"(r[2]), "=r"(r[3]) : "r"(addr));
}

__device__ __forceinline__ void cp16(void* dst_smem, const void* src, bool pred) {
    uint32_t d = (uint32_t)__cvta_generic_to_shared(dst_smem);
    int sz = pred ? 16 : 0;
    asm volatile("cp.async.cg.shared.global [%0], [%1], 16, %2;\n"
                 :: "r"(d), "l"(src), "r"(sz));
}
#define CP_COMMIT() asm volatile("cp.async.commit_group;\n" ::: "memory")
#define CP_WAIT1()  asm volatile("cp.async.wait_group 1;\n" ::: "memory")
#define CP_WAIT3()  asm volatile("cp.async.wait_group 3;\n" ::: "memory")

// ---------------- init ----------------
__global__ void init_kernel(const float* __restrict__ b_ih1, const float* __restrict__ b_hh1,
                            const float* __restrict__ b_ih2, const float* __restrict__ b_hh2,
                            float* out) {
    int idx = blockIdx.x * blockDim.x + threadIdx.x;   // 0..393215
    if (idx < 2 * BU) ((uint32_t*)g_h12b)[idx] = 0u;   // 4*BU bf16 = 2*BU u32
    else if (idx < 2 * BU + 65536) g_c1[idx - 2 * BU] = 0.0f;
    else if (idx < 2 * BU + 131072) g_c2[idx - 2 * BU - 65536] = 0.0f;
    if (idx < G4) {
        g_bias1[idx] = b_ih1[idx] + b_hh1[idx];
        g_bias2[idx] = b_ih2[idx] + b_hh2[idx];
    }
    if (idx == 0) out[0] = 0.0f;
}

// ---------------- f32 -> bf16 convert (n multiple of 4) ----------------
__global__ void cvt_bf16(const float* __restrict__ in, __nv_bfloat16* __restrict__ out, int n) {
    int i = (blockIdx.x * blockDim.x + threadIdx.x) * 4;
    if (i < n) {
        float4 v = *(const float4*)(in + i);
        __nv_bfloat162* o = (__nv_bfloat162*)(out + i);
        o[0] = __floats2bfloat162_rn(v.x, v.y);
        o[1] = __floats2bfloat162_rn(v.z, v.w);
    }
}

// pack w_ih2[:, :512] -> bf16 [2048][512]
__global__ void cvt_wih2(const float* __restrict__ in, __nv_bfloat16* __restrict__ out) {
    int i = (blockIdx.x * blockDim.x + threadIdx.x) * 4;  // over 2048*512
    int n = i >> 9, k = i & 511;
    float4 v = *(const float4*)(in + n * 1024 + k);
    __nv_bfloat162* o = (__nv_bfloat162*)(out + i);
    o[0] = __floats2bfloat162_rn(v.x, v.y);
    o[1] = __floats2bfloat162_rn(v.z, v.w);
}

// ---------------- fuse cell2 weights -> bf16 [2048][1024] ----------------
__global__ void w2cat_kernel(const float* __restrict__ w_ih2, const float* __restrict__ w_hh2) {
    int idx = blockIdx.x * blockDim.x + threadIdx.x;
    int n = idx >> 10, k = idx & 1023;
    float v = (k < EDIM) ? w_ih2[n * 1024 + EDIM + k] : w_hh2[n * EDIM + (k - EDIM)];
    g_W2catb[idx] = __float2bfloat16(v);
}

// =====================================================================
// bf16_gemm256: C[M,N] = A @ W^T (+bias). 128x256 tile, BK=32, 3-stage
// cp.async, ldmatrix + m16n8k16. 256 thr, 8 warps (2M x 4N), warp 64x64.
// dyn smem = 3*(128+256)*PB*2 = 92160 B.
// =====================================================================
#define BGEMM_SMEM 92160
__global__ __launch_bounds__(256)
void bf16_gemm256(const __nv_bfloat16* __restrict__ A, size_t sT, size_t sB,
                  const __nv_bfloat16* __restrict__ W, int ldW,
                  const float* __restrict__ bias,
                  float* __restrict__ C, int N, int kTot) {
    extern __shared__ __nv_bfloat16 sm[];
    __nv_bfloat16* AsB = sm;                 // [3][128*PB]
    __nv_bfloat16* BsB = sm + 3 * 128 * PB;  // [3][256*PB]

    const int tid = threadIdx.x;
    const int lane = tid & 31, wid = tid >> 5;
    const int g = lane >> 2, t = lane & 3;
    const int warpM = wid >> 2, warpN = wid & 3;
    const __nv_bfloat16* Ab = A + (size_t)blockIdx.y * sT;
    const int n0 = blockIdx.x * 256;

    const int aoff = (lane & 15) * PB + ((lane >> 4) & 1) * 8;
    const int boff = (((lane >> 4) & 1) * 8 + (lane & 7)) * PB + ((lane >> 3) & 1) * 8;

    float acc[4][8][4];
#pragma unroll
    for (int i = 0; i < 4; i++)
#pragma unroll
        for (int j = 0; j < 8; j++)
#pragma unroll
            for (int r = 0; r < 4; r++) acc[i][j][r] = 0.0f;

    const int nch = kTot >> 5;

    auto issue = [&](int ch) {
        if (ch < nch) {
            int st = ch % 3;
            __nv_bfloat16* Ad = AsB + st * 128 * PB;
            __nv_bfloat16* Bd = BsB + st * 256 * PB;
            int k0 = ch * 32;
#pragma unroll
            for (int it = 0; it < 2; it++) {
                int c = it * 256 + tid;
                int row = c >> 2, seg = (c & 3) * 8;
                cp16(Ad + row * PB + seg, Ab + (size_t)row * sB + k0 + seg, true);
            }
#pragma unroll
            for (int it = 0; it < 4; it++) {
                int c = it * 256 + tid;
                int row = c >> 2, seg = (c & 3) * 8;
                int gn = n0 + row;
                cp16(Bd + row * PB + seg, W + (size_t)gn * ldW + k0 + seg, gn < N);
            }
        }
        CP_COMMIT();
    };

    issue(0);
    issue(1);

    for (int ch = 0; ch < nch; ch++) {
        CP_WAIT1();
        __syncthreads();
        issue(ch + 2);

        int st = ch % 3;
        uint32_t smA = (uint32_t)__cvta_generic_to_shared(AsB + st * 128 * PB);
        uint32_t smB = (uint32_t)__cvta_generic_to_shared(BsB + st * 256 * PB);
#pragma unroll
        for (int ks = 0; ks < 2; ks++) {
            const int kb = ks * 16;
            uint32_t afr[4][4];
#pragma unroll
            for (int mt = 0; mt < 4; mt++) {
                int R = warpM * 64 + mt * 16;
                ldsm4(afr[mt], smA + (uint32_t)(R * PB + kb + aoff) * 2);
            }
            uint32_t bfr[8][2];
#pragma unroll
            for (int np = 0; np < 4; np++) {
                int Cc = warpN * 64 + np * 16;
                uint32_t rr[4];
                ldsm4(rr, smB + (uint32_t)(Cc * PB + kb + boff) * 2);
                bfr[2 * np][0] = rr[0]; bfr[2 * np][1] = rr[1];
                bfr[2 * np + 1][0] = rr[2]; bfr[2 * np + 1][1] = rr[3];
            }
#pragma unroll
            for (int mt = 0; mt < 4; mt++)
#pragma unroll
                for (int nt = 0; nt < 8; nt++)
                    mma_bf16(acc[mt][nt], afr[mt], bfr[nt]);
        }
        __syncthreads();
    }

#pragma unroll
    for (int mt = 0; mt < 4; mt++) {
        size_t gm0 = (size_t)blockIdx.y * 128 + warpM * 64 + mt * 16 + g;
#pragma unroll
        for (int nt = 0; nt < 8; nt++) {
            int gc = n0 + warpN * 64 + nt * 8 + 2 * t;
#pragma unroll
            for (int r = 0; r < 4; r++) {
                size_t gm = gm0 + (r >= 2 ? 8 : 0);
                int cc = gc + (r & 1);
                if (cc < N) {
                    float b0 = bias ? bias[cc] : 0.0f;
                    C[gm * N + cc] = acc[mt][nt][r] + b0;
                }
            }
        }
    }
}

// =====================================================================
// cell_fused (bf16): one LSTM cell phase. 128 CTAs x 128 threads.
// CTA bx: j-group j0 = (bx>>1)*8, row half rb = (bx&1)*64 (64 batch rows).
// gates[64,32] = A[rb:rb+64, Kt] @ Wrows^T, fused f32 LSTM pointwise.
// A: k<512 from A0[m*1024+k], k>=512 from A1[m*1024+k] (both bf16).
// 4-stage cp.async + ldmatrix + m16n8k16.
// dyn smem = 4*(64*PB + 32*PB)*2 = 30720 B.
// =====================================================================
#define ASTG (64 * PB)
#define WSTG (32 * PB)
#define CELL_SMEM (4 * (ASTG + WSTG) * 2)
__global__ __launch_bounds__(128, 1)
void cell_fused(const __nv_bfloat16* __restrict__ A0, const __nv_bfloat16* __restrict__ A1,
                const __nv_bfloat16* __restrict__ W, int ldW, int Kt,
                const float* __restrict__ xpre, const float* __restrict__ bias,
                float* __restrict__ c, __nv_bfloat16* __restrict__ hout, int hoff,
                __nv_bfloat16* __restrict__ hcopy) {
    extern __shared__ __nv_bfloat16 smc[];
    __nv_bfloat16* AsB = smc;             // [4][ASTG]
    __nv_bfloat16* WsB = smc + 4 * ASTG;  // [4][WSTG]

    const int tid = threadIdx.x;
    const int lane = tid & 31, wid = tid >> 5;       // 4 warps
    const int g = lane >> 2, t = lane & 3;
    const int j0 = (blockIdx.x >> 1) * 8;
    const int rb = (blockIdx.x & 1) * 64;            // row base

    const int aoff = (lane & 15) * PB + ((lane >> 4) & 1) * 8;
    const int boff = (((lane >> 4) & 1) * 8 + (lane & 7)) * PB + ((lane >> 3) & 1) * 8;

    float acc[4][4];
#pragma unroll
    for (int nt = 0; nt < 4; nt++)
#pragma unroll
        for (int r = 0; r < 4; r++) acc[nt][r] = 0.0f;

    const int nch = Kt >> 5;
    // W loaders: all 128 threads, row lc = tid>>2 (0..31), seg (tid&3)*8
    const int lcw = tid >> 2, segw = (tid & 3) * 8;
    const int nw = (lcw >> 3) * 512 + j0 + (lcw & 7);

    auto issue = [&](int ch) {
        if (ch < nch) {
            int st = ch & 3;
            int k0 = ch << 5;
            const __nv_bfloat16* src = (k0 < 512) ? A0 : A1;
            __nv_bfloat16* Ad = AsB + st * ASTG;
#pragma unroll
            for (int it = 0; it < 2; it++) {
                int cc = it * 128 + tid;             // 0..255
                int row = cc >> 2, seg = (cc & 3) * 8;
                cp16(Ad + row * PB + seg, src + (rb + row) * 1024 + k0 + seg, true);
            }
            cp16(WsB + st * WSTG + lcw * PB + segw,
                 W + (size_t)nw * ldW + k0 + segw, true);
        }
        CP_COMMIT();
    };

    issue(0); issue(1); issue(2);

    for (int ch = 0; ch < nch; ch++) {
        issue(ch + 3);
        CP_WAIT3();
        __syncthreads();

        int st = ch & 3;
        uint32_t smA = (uint32_t)__cvta_generic_to_shared(AsB + st * ASTG);
        uint32_t smB = (uint32_t)__cvta_generic_to_shared(WsB + st * WSTG);
        const int row = wid * 16;                    // 0,16,32,48
#pragma unroll
        for (int ks = 0; ks < 2; ks++) {
            const int kb = ks * 16;
            uint32_t afr[4];
            ldsm4(afr, smA + (uint32_t)(row * PB + kb + aoff) * 2);
            uint32_t bfr[4][2];
#pragma unroll
            for (int np = 0; np < 2; np++) {
                uint32_t rr[4];
                ldsm4(rr, smB + (uint32_t)((np * 16) * PB + kb + boff) * 2);
                bfr[2 * np][0] = rr[0]; bfr[2 * np][1] = rr[1];
                bfr[2 * np + 1][0] = rr[2]; bfr[2 * np + 1][1] = rr[3];
            }
#pragma unroll
            for (int nt = 0; nt < 4; nt++)
                mma_bf16(acc[nt], afr, bfr[nt]);
        }
        __syncthreads();
    }

    // stage gates to smem (f32, pitch SMPF) — reuse smem; rows 0..63 local
    float* Ss = (float*)smc;
#pragma unroll
    for (int nt = 0; nt < 4; nt++) {
#pragma unroll
        for (int r = 0; r < 4; r++) {
            int row = wid * 16 + g + ((r & 2) ? 8 : 0);
            int col = nt * 8 + 2 * t + (r & 1);
            Ss[row * SMPF + col] = acc[nt][r];
        }
    }
    __syncthreads();

    // fused LSTM pointwise: 64 rows x 8 j-cols (f32 state)
#pragma unroll
    for (int it = 0; it < 4; it++) {
        int idx = it * 128 + tid;                    // 0..511
        int rl = idx >> 3, jj = idx & 7;
        int row = rb + rl;
        int j = j0 + jj;
        float gi = Ss[rl * SMPF + jj];
        float gf = Ss[rl * SMPF + 8 + jj];
        float gg = Ss[rl * SMPF + 16 + jj];
        float go = Ss[rl * SMPF + 24 + jj];
        if (xpre) {
            const float* xp = xpre + row * G4 + j;
            gi += xp[0]; gf += xp[512]; gg += xp[1024]; go += xp[1536];
        }
        if (bias) {
            gi += bias[j]; gf += bias[512 + j];
            gg += bias[1024 + j]; go += bias[1536 + j];
        }
        float cv = c[row * 512 + j];
        float cn = sigmoidf_(gf) * cv + sigmoidf_(gi) * tanhf(gg);
        c[row * 512 + j] = cn;
        float h = sigmoidf_(go) * tanhf(cn);
        __nv_bfloat16 hb = __float2bfloat16(h);
        hout[row * 1024 + hoff + j] = hb;
        if (hcopy) hcopy[row * 512 + j] = hb;
    }
}

// ---------------- argmax over vocab ----------------
__global__ void argmax_kernel(const float* __restrict__ oh) {
    int r = blockIdx.x;
    int s = r >> 7, b = r & 127;
    const float* row = oh + (size_t)b * (DECL * VOC) + (size_t)(s + 1) * VOC;
    __shared__ float sv[128];
    __shared__ int si[128];
    int tid = threadIdx.x;
    float best = -3.4e38f; int bi = 0;
    for (int i = tid; i < VOC; i += 128) {
        float v = row[i];
        if (v > best) { best = v; bi = i; }
    }
    sv[tid] = best; si[tid] = bi;
    __syncthreads();
    for (int o = 64; o > 0; o >>= 1) {
        if (tid < o) {
            if (sv[tid + o] > sv[tid] || (sv[tid + o] == sv[tid] && si[tid + o] < si[tid])) {
                sv[tid] = sv[tid + o]; si[tid] = si[tid + o];
            }
        }
        __syncthreads();
    }
    if (tid == 0) g_labels[r] = si[0];
}

// ---------------- per-row NLL ----------------
__global__ void loss_kernel() {
    int r = blockIdx.x;
    const float* row = g_logits + (size_t)r * VOC;
    __shared__ float red[256];
    int tid = threadIdx.x;
    float m = -3.4e38f;
    for (int i = tid; i < VOC; i += 256) m = fmaxf(m, row[i]);
    red[tid] = m; __syncthreads();
    for (int o = 128; o > 0; o >>= 1) {
        if (tid < o) red[tid] = fmaxf(red[tid], red[tid + o]);
        __syncthreads();
    }
    float mall = red[0];
    __syncthreads();
    float sacc = 0.f;
    for (int i = tid; i < VOC; i += 256) sacc += expf(row[i] - mall);
    red[tid] = sacc; __syncthreads();
    for (int o = 128; o > 0; o >>= 1) {
        if (tid < o) red[tid] += red[tid + o];
        __syncthreads();
    }
    if (tid == 0) {
        int lab = g_labels[r];
        g_rowloss[r] = (mall + logf(red[0])) - row[lab];
    }
}

__global__ void final_reduce(float* out) {
    __shared__ float red[256];
    int tid = threadIdx.x;
    float s = 0.f;
    for (int i = tid; i < DSTEPS * BATCH; i += 256) s += g_rowloss[i];
    red[tid] = s; __syncthreads();
    for (int o = 128; o > 0; o >>= 1) {
        if (tid < o) red[tid] += red[tid + o];
        __syncthreads();
    }
    if (tid == 0) out[0] = red[0] * (1.0f / 128.0f);
}

// ---------------- host ----------------
extern "C" void kernel_launch(void* const* d_in, const int* in_sizes, int n_in,
                              void* d_out, int out_size) {
    const float* feat    = (const float*)d_in[0];
    const float* caption = (const float*)d_in[1];
    const float* oh      = (const float*)d_in[2];
    const float* w_ih1   = (const float*)d_in[3];
    const float* w_hh1   = (const float*)d_in[4];
    const float* b_ih1   = (const float*)d_in[5];
    const float* b_hh1   = (const float*)d_in[6];
    const float* w_ih2   = (const float*)d_in[7];
    const float* w_hh2   = (const float*)d_in[8];
    const float* b_ih2   = (const float*)d_in[9];
    const float* b_hh2   = (const float*)d_in[10];
    const float* w_out   = (const float*)d_in[11];
    const float* b_out   = (const float*)d_in[12];
    float* out = (float*)d_out;

    float *pX1, *pWx2, *pB1, *pB2, *pC1, *pC2, *pLog;
    __nv_bfloat16 *pH12b, *pW2b16, *pWhh1b, *pFb, *pCb, *pW1b, *pW2b, *pWOb, *pH2b;
    cudaGetSymbolAddress((void**)&pX1,   g_X1pre);
    cudaGetSymbolAddress((void**)&pWx2,  g_Wx2);
    cudaGetSymbolAddress((void**)&pB1,   g_bias1);
    cudaGetSymbolAddress((void**)&pB2,   g_bias2);
    cudaGetSymbolAddress((void**)&pC1,   g_c1);
    cudaGetSymbolAddress((void**)&pC2,   g_c2);
    cudaGetSymbolAddress((void**)&pLog,  g_logits);
    cudaGetSymbolAddress((void**)&pH12b, g_h12b);
    cudaGetSymbolAddress((void**)&pW2b16, g_W2catb);
    cudaGetSymbolAddress((void**)&pWhh1b, g_whh1b);
    cudaGetSymbolAddress((void**)&pFb,   g_featb);
    cudaGetSymbolAddress((void**)&pCb,   g_capb);
    cudaGetSymbolAddress((void**)&pW1b,  g_wih1b);
    cudaGetSymbolAddress((void**)&pW2b,  g_wih2b);
    cudaGetSymbolAddress((void**)&pWOb,  g_woutb);
    cudaGetSymbolAddress((void**)&pH2b,  g_H2b);

    static bool init_done = false;
    static cudaStream_t s1, s2;
    static cudaEvent_t evStart, evCap, evF[NFCH], ev1[NSTEP], ev2[NSTEP];
    if (!init_done) {
        cudaFuncSetAttribute(bf16_gemm256,
                             cudaFuncAttributeMaxDynamicSharedMemorySize, BGEMM_SMEM);
        cudaFuncSetAttribute(cell_fused,
                             cudaFuncAttributeMaxDynamicSharedMemorySize, CELL_SMEM);
        cudaStreamCreateWithFlags(&s1, cudaStreamNonBlocking);
        cudaStreamCreateWithFlags(&s2, cudaStreamNonBlocking);
        cudaEventCreateWithFlags(&evStart, cudaEventDisableTiming);
        cudaEventCreateWithFlags(&evCap, cudaEventDisableTiming);
        for (int i = 0; i < NFCH; i++)
            cudaEventCreateWithFlags(&evF[i], cudaEventDisableTiming);
        for (int i = 0; i < NSTEP; i++) {
            cudaEventCreateWithFlags(&ev1[i], cudaEventDisableTiming);
            cudaEventCreateWithFlags(&ev2[i], cudaEventDisableTiming);
        }
        init_done = true;
    }

    // ---- minimal serial prefix on stream 0 (only what the recurrence needs now) ----
    init_kernel<<<1536, 256>>>(b_ih1, b_hh1, b_ih2, b_hh2, out);
    w2cat_kernel<<<8192, 256>>>(w_ih2, w_hh2);
    {
        int nf = BATCH * TFRM * FEATD;
        cvt_bf16<<<nf / 1024, 256>>>(feat, pFb, nf);
        int nw = G4 * FEATD;
        cvt_bf16<<<nw / 1024, 256>>>(w_ih1, pW1b, nw);
        cvt_bf16<<<(G4 * EDIM) / 1024, 256>>>(w_hh1, pWhh1b, G4 * EDIM);
    }
    cudaEventRecord(evStart, 0);
    cudaStreamWaitEvent(s1, evStart, 0);
    cudaStreamWaitEvent(s2, evStart, 0);

    // ---- stream 0: chunked feat GEMM (overlaps recurrence after chunk 0) ----
    // X1pre = feat @ w_ih1^T + bias1   [10240 x 2048], 20 timesteps per chunk
    for (int cfh = 0; cfh < NFCH; cfh++) {
        bf16_gemm256<<<dim3(8, 20), 256, BGEMM_SMEM>>>(
            pFb + (size_t)cfh * 20 * FEATD, (size_t)FEATD, (size_t)TFRM * FEATD,
            pW1b, FEATD, pB1, pX1 + (size_t)cfh * 20 * BATCH * G4, G4, FEATD);
        cudaEventRecord(evF[cfh], 0);
    }

    // ---- stream 0: caption path (overlaps recurrence; needed at t=TFRM) ----
    {
        int nc = BATCH * DECL * EDIM;
        cvt_bf16<<<nc / 1024, 256>>>(caption, pCb, nc);
        cvt_wih2<<<(G4 * EDIM) / 1024, 256>>>(w_ih2, pW2b);
    }
    bf16_gemm256<<<dim3(8, 29), 256, BGEMM_SMEM>>>(
        pCb, (size_t)EDIM, (size_t)DECL * EDIM, pW2b, EDIM, nullptr, pWx2, G4, EDIM);
    cudaEventRecord(evCap, 0);

    // ---- stream 0: rest of the tail prep (overlaps recurrence) ----
    cvt_bf16<<<(VOC * EDIM) / 1024, 256>>>(w_out, pWOb, VOC * EDIM);
    argmax_kernel<<<DSTEPS * BATCH, 128>>>(oh);

    // ---- recurrence: two overlapped chains (bf16 h-state) ----
    for (int t = 0; t < NSTEP; t++) {
        bool enc = t < TFRM;
        int s = t - TFRM;
        __nv_bfloat16* bPrev = pH12b + (size_t)((t + 3) & 3) * BU;
        __nv_bfloat16* bCur  = pH12b + (size_t)(t & 3) * BU;

        if (enc && (t % 20) == 0) cudaStreamWaitEvent(s1, evF[t / 20], 0);
        if (t >= 4) cudaStreamWaitEvent(s1, ev2[t - 4], 0);
        cell_fused<<<128, 128, CELL_SMEM, s1>>>(
            bPrev, bPrev, pWhh1b, EDIM, 512,
            enc ? (pX1 + (size_t)t * BATCH * G4) : nullptr,
            enc ? nullptr : pB1,
            pC1, bCur, 0, nullptr);
        cudaEventRecord(ev1[t], s1);

        if (t == TFRM) cudaStreamWaitEvent(s2, evCap, 0);
        cudaStreamWaitEvent(s2, ev1[t], 0);
        cell_fused<<<128, 128, CELL_SMEM, s2>>>(
            bCur, bPrev, pW2b16, 1024, 1024,
            enc ? nullptr : (pWx2 + (size_t)s * BATCH * G4),
            pB2, pC2, bCur, 512,
            enc ? nullptr : (pH2b + (size_t)s * BATCH * EDIM));
        cudaEventRecord(ev2[t], s2);
    }

    cudaStreamWaitEvent(0, ev1[NSTEP - 1], 0);
    cudaStreamWaitEvent(0, ev2[NSTEP - 1], 0);

    // logits = H2b @ w_out^T + b_out   [3712 x 6000]
    bf16_gemm256<<<dim3(24, 29), 256, BGEMM_SMEM>>>(
        pH2b, (size_t)BATCH * EDIM, (size_t)EDIM, pWOb, EDIM, b_out, pLog, VOC, EDIM);
    loss_kernel<<<DSTEPS * BATCH, 256>>>();
    final_reduce<<<1, 256>>>(out);
}

// round 16
// speedup vs baseline: 1.1147x; 1.1147x over previous
#include <cuda_runtime.h>
#include <cuda_bf16.h>
#include <stdint.h>

#define BATCH 128
#define TFRM 80
#define DECL 30
#define DSTEPS 29
#define NSTEP (TFRM + DSTEPS)   // 109
#define EDIM 512
#define G4 2048
#define FEATD 4096
#define VOC 6000
#define PB 40             // bf16 smem pitch (A tiles)
#define SMPF 36           // f32 gate-staging pitch
#define BU (BATCH * 1024) // one h12 buffer (elems)
#define WP1 520           // resident W pitch, cell1 (K=512)
#define WP2 1032          // resident W pitch, cell2 (K=1024)
#define ASTG (64 * PB)
#define C1_SMEM ((32 * WP1 + 4 * ASTG) * 2)   // 53760 B
#define C2_SMEM ((32 * WP2 + 4 * ASTG) * 2)   // 86528 B

// ---------------- scratch (static device globals; no allocation) ----------------
__device__ float g_X1pre[TFRM * BATCH * G4];
__device__ float g_Wx2[DSTEPS * BATCH * G4];
__device__ float g_bias1[G4];
__device__ float g_bias2[G4];
__device__ float g_c1[BATCH * EDIM];
__device__ float g_c2[BATCH * EDIM];
__device__ float g_logits[DSTEPS * BATCH * VOC];
__device__ int   g_labels[DSTEPS * BATCH];
__device__ float g_rowloss[DSTEPS * BATCH];
__device__ unsigned g_cnt1[NSTEP];
__device__ unsigned g_cnt2[NSTEP];
// bf16 staging
__device__ __nv_bfloat16 g_h12b[4 * BU];              // 4-deep ping-pong [h1 | h2]
__device__ __nv_bfloat16 g_W2catb[G4 * 1024];         // [w_ih2[:,E:2E] ; w_hh2] bf16
__device__ __nv_bfloat16 g_whh1b[G4 * EDIM];          // w_hh1 bf16
__device__ __nv_bfloat16 g_featb[BATCH * TFRM * FEATD];
__device__ __nv_bfloat16 g_capb[BATCH * DECL * EDIM];
__device__ __nv_bfloat16 g_wih1b[G4 * FEATD];
__device__ __nv_bfloat16 g_wih2b[G4 * EDIM];          // packed first-512 cols
__device__ __nv_bfloat16 g_woutb[VOC * EDIM];
__device__ __nv_bfloat16 g_H2b[DSTEPS * BATCH * EDIM];

__device__ __forceinline__ float sigmoidf_(float x) {
    return 1.0f / (1.0f + expf(-x));
}

__device__ __forceinline__ void mma_bf16(float* d, const uint32_t* a, const uint32_t* b) {
    asm volatile(
        "mma.sync.aligned.m16n8k16.row.col.f32.bf16.bf16.f32 "
        "{%0,%1,%2,%3}, {%4,%5,%6,%7}, {%8,%9}, {%0,%1,%2,%3};"
        : "+f"(d[0]), "+f"(d[1]), "+f"(d[2]), "+f"(d[3])
        : "r"(a[0]), "r"(a[1]), "r"(a[2]), "r"(a[3]), "r"(b[0]), "r"(b[1]));
}

__device__ __forceinline__ void ldsm4(uint32_t* r, uint32_t addr) {
    asm volatile("ldmatrix.sync.aligned.m8n8.x4.shared.b16 {%0,%1,%2,%3}, [%4];"
                 : "=r"(r[0]), "=r"(r[1]), "=r"(r[2]), "=r"(r[3]) : "r"(addr));
}

__device__ __forceinline__ void cp16(void* dst_smem, const void* src, bool pred) {
    uint32_t d = (uint32_t)__cvta_generic_to_shared(dst_smem);
    int sz = pred ? 16 : 0;
    asm volatile("cp.async.cg.shared.global [%0], [%1], 16, %2;\n"
                 :: "r"(d), "l"(src), "r"(sz));
}
#define CP_COMMIT() asm volatile("cp.async.commit_group;\n" ::: "memory")
#define CP_WAIT0()  asm volatile("cp.async.wait_group 0;\n" ::: "memory")
#define CP_WAIT1()  asm volatile("cp.async.wait_group 1;\n" ::: "memory")
#define CP_WAIT3()  asm volatile("cp.async.wait_group 3;\n" ::: "memory")

// ---- L2-scoped flag sync (no L1 flushes; data path is .cg = L2-coherent) ----
__device__ __forceinline__ unsigned ld_acq(const unsigned* p) {
    unsigned v;
    asm volatile("ld.acquire.gpu.global.u32 %0, [%1];" : "=r"(v) : "l"(p) : "memory");
    return v;
}
__device__ __forceinline__ void red_rel(unsigned* p) {
    asm volatile("red.release.gpu.global.add.u32 [%0], %1;" :: "l"(p), "r"(1u) : "memory");
}
__device__ __forceinline__ void wait_cnt(const unsigned* p) {
    if (threadIdx.x == 0) {
        while (ld_acq(p) < 128u) __nanosleep(64);
    }
    __syncthreads();
}
__device__ __forceinline__ void stcg_bf16(__nv_bfloat16* p, __nv_bfloat16 v) {
    unsigned short b = __bfloat16_as_ushort(v);
    asm volatile("st.global.cg.u16 [%0], %1;" :: "l"(p), "h"(b) : "memory");
}

// ---------------- init ----------------
__global__ void init_kernel(const float* __restrict__ b_ih1, const float* __restrict__ b_hh1,
                            const float* __restrict__ b_ih2, const float* __restrict__ b_hh2,
                            float* out) {
    int idx = blockIdx.x * blockDim.x + threadIdx.x;   // 0..393215
    if (idx < 2 * BU) ((uint32_t*)g_h12b)[idx] = 0u;   // 4*BU bf16 = 2*BU u32
    else if (idx < 2 * BU + 65536) g_c1[idx - 2 * BU] = 0.0f;
    else if (idx < 2 * BU + 131072) g_c2[idx - 2 * BU - 65536] = 0.0f;
    if (idx < G4) {
        g_bias1[idx] = b_ih1[idx] + b_hh1[idx];
        g_bias2[idx] = b_ih2[idx] + b_hh2[idx];
    }
    if (idx < NSTEP) { g_cnt1[idx] = 0u; g_cnt2[idx] = 0u; }
    if (idx == 0) out[0] = 0.0f;
}

// ---------------- f32 -> bf16 convert (n multiple of 4) ----------------
__global__ void cvt_bf16(const float* __restrict__ in, __nv_bfloat16* __restrict__ out, int n) {
    int i = (blockIdx.x * blockDim.x + threadIdx.x) * 4;
    if (i < n) {
        float4 v = *(const float4*)(in + i);
        __nv_bfloat162* o = (__nv_bfloat162*)(out + i);
        o[0] = __floats2bfloat162_rn(v.x, v.y);
        o[1] = __floats2bfloat162_rn(v.z, v.w);
    }
}

// pack w_ih2[:, :512] -> bf16 [2048][512]
__global__ void cvt_wih2(const float* __restrict__ in, __nv_bfloat16* __restrict__ out) {
    int i = (blockIdx.x * blockDim.x + threadIdx.x) * 4;  // over 2048*512
    int n = i >> 9, k = i & 511;
    float4 v = *(const float4*)(in + n * 1024 + k);
    __nv_bfloat162* o = (__nv_bfloat162*)(out + i);
    o[0] = __floats2bfloat162_rn(v.x, v.y);
    o[1] = __floats2bfloat162_rn(v.z, v.w);
}

// ---------------- fuse cell2 weights -> bf16 [2048][1024] ----------------
__global__ void w2cat_kernel(const float* __restrict__ w_ih2, const float* __restrict__ w_hh2) {
    int idx = blockIdx.x * blockDim.x + threadIdx.x;
    int n = idx >> 10, k = idx & 1023;
    float v = (k < EDIM) ? w_ih2[n * 1024 + EDIM + k] : w_hh2[n * EDIM + (k - EDIM)];
    g_W2catb[idx] = __float2bfloat16(v);
}

// =====================================================================
// bf16_gemm256: C[M,N] = A @ W^T (+bias). 128x256 tile, BK=32, 3-stage
// cp.async, ldmatrix + m16n8k16. dyn smem = 3*(128+256)*PB*2 = 92160 B.
// =====================================================================
#define BGEMM_SMEM 92160
__global__ __launch_bounds__(256)
void bf16_gemm256(const __nv_bfloat16* __restrict__ A, size_t sT, size_t sB,
                  const __nv_bfloat16* __restrict__ W, int ldW,
                  const float* __restrict__ bias,
                  float* __restrict__ C, int N, int kTot) {
    extern __shared__ __nv_bfloat16 sm[];
    __nv_bfloat16* AsB = sm;                 // [3][128*PB]
    __nv_bfloat16* BsB = sm + 3 * 128 * PB;  // [3][256*PB]

    const int tid = threadIdx.x;
    const int lane = tid & 31, wid = tid >> 5;
    const int g = lane >> 2, t = lane & 3;
    const int warpM = wid >> 2, warpN = wid & 3;
    const __nv_bfloat16* Ab = A + (size_t)blockIdx.y * sT;
    const int n0 = blockIdx.x * 256;

    const int aoff = (lane & 15) * PB + ((lane >> 4) & 1) * 8;
    const int boff = (((lane >> 4) & 1) * 8 + (lane & 7)) * PB + ((lane >> 3) & 1) * 8;

    float acc[4][8][4];
#pragma unroll
    for (int i = 0; i < 4; i++)
#pragma unroll
        for (int j = 0; j < 8; j++)
#pragma unroll
            for (int r = 0; r < 4; r++) acc[i][j][r] = 0.0f;

    const int nch = kTot >> 5;

    auto issue = [&](int ch) {
        if (ch < nch) {
            int st = ch % 3;
            __nv_bfloat16* Ad = AsB + st * 128 * PB;
            __nv_bfloat16* Bd = BsB + st * 256 * PB;
            int k0 = ch * 32;
#pragma unroll
            for (int it = 0; it < 2; it++) {
                int c = it * 256 + tid;
                int row = c >> 2, seg = (c & 3) * 8;
                cp16(Ad + row * PB + seg, Ab + (size_t)row * sB + k0 + seg, true);
            }
#pragma unroll
            for (int it = 0; it < 4; it++) {
                int c = it * 256 + tid;
                int row = c >> 2, seg = (c & 3) * 8;
                int gn = n0 + row;
                cp16(Bd + row * PB + seg, W + (size_t)gn * ldW + k0 + seg, gn < N);
            }
        }
        CP_COMMIT();
    };

    issue(0);
    issue(1);

    for (int ch = 0; ch < nch; ch++) {
        CP_WAIT1();
        __syncthreads();
        issue(ch + 2);

        int st = ch % 3;
        uint32_t smA = (uint32_t)__cvta_generic_to_shared(AsB + st * 128 * PB);
        uint32_t smB = (uint32_t)__cvta_generic_to_shared(BsB + st * 256 * PB);
#pragma unroll
        for (int ks = 0; ks < 2; ks++) {
            const int kb = ks * 16;
            uint32_t afr[4][4];
#pragma unroll
            for (int mt = 0; mt < 4; mt++) {
                int R = warpM * 64 + mt * 16;
                ldsm4(afr[mt], smA + (uint32_t)(R * PB + kb + aoff) * 2);
            }
            uint32_t bfr[8][2];
#pragma unroll
            for (int np = 0; np < 4; np++) {
                int Cc = warpN * 64 + np * 16;
                uint32_t rr[4];
                ldsm4(rr, smB + (uint32_t)(Cc * PB + kb + boff) * 2);
                bfr[2 * np][0] = rr[0]; bfr[2 * np][1] = rr[1];
                bfr[2 * np + 1][0] = rr[2]; bfr[2 * np + 1][1] = rr[3];
            }
#pragma unroll
            for (int mt = 0; mt < 4; mt++)
#pragma unroll
                for (int nt = 0; nt < 8; nt++)
                    mma_bf16(acc[mt][nt], afr[mt], bfr[nt]);
        }
        __syncthreads();
    }

#pragma unroll
    for (int mt = 0; mt < 4; mt++) {
        size_t gm0 = (size_t)blockIdx.y * 128 + warpM * 64 + mt * 16 + g;
#pragma unroll
        for (int nt = 0; nt < 8; nt++) {
            int gc = n0 + warpN * 64 + nt * 8 + 2 * t;
#pragma unroll
            for (int r = 0; r < 4; r++) {
                size_t gm = gm0 + (r >= 2 ? 8 : 0);
                int cc = gc + (r & 1);
                if (cc < N) {
                    float b0 = bias ? bias[cc] : 0.0f;
                    C[gm * N + cc] = acc[mt][nt][r] + b0;
                }
            }
        }
    }
}

// =====================================================================
// cell_step: one LSTM cell phase body (resident W in smem, 64 rows x 8 j).
// A: k<512 from A0[(rb+row)*1024+k], k>=512 from A1 (both bf16, via cp.async.cg).
// =====================================================================
template <int KT, int WP>
__device__ __forceinline__ void cell_step(
    const __nv_bfloat16* A0, const __nv_bfloat16* A1,
    const __nv_bfloat16* Wsm, __nv_bfloat16* Asm,
    const float* xpre, const float* bias,
    float* c, __nv_bfloat16* hout, int hoff, __nv_bfloat16* hcopy,
    int j0, int rb) {

    const int tid = threadIdx.x;
    const int lane = tid & 31, wid = tid >> 5;
    const int g = lane >> 2, t4 = lane & 3;
    const int aoff = (lane & 15) * PB + ((lane >> 4) & 1) * 8;
    const int boffW = (((lane >> 4) & 1) * 8 + (lane & 7)) * WP + ((lane >> 3) & 1) * 8;

    float acc[4][4];
#pragma unroll
    for (int nt = 0; nt < 4; nt++)
#pragma unroll
        for (int r = 0; r < 4; r++) acc[nt][r] = 0.0f;

    const int nch = KT >> 5;
    const uint32_t smW = (uint32_t)__cvta_generic_to_shared(Wsm);

    auto issue = [&](int ch) {
        if (ch < nch) {
            int st = ch & 3;
            int k0 = ch << 5;
            const __nv_bfloat16* src = (k0 < 512) ? A0 : A1;
            __nv_bfloat16* Ad = Asm + st * ASTG;
#pragma unroll
            for (int it = 0; it < 2; it++) {
                int cc = it * 128 + tid;
                int row = cc >> 2, seg = (cc & 3) * 8;
                cp16(Ad + row * PB + seg, src + (size_t)(rb + row) * 1024 + k0 + seg, true);
            }
        }
        CP_COMMIT();
    };

    issue(0); issue(1); issue(2);

    for (int ch = 0; ch < nch; ch++) {
        issue(ch + 3);
        CP_WAIT3();
        __syncthreads();

        int st = ch & 3;
        int k0 = ch << 5;
        uint32_t smA = (uint32_t)__cvta_generic_to_shared(Asm + st * ASTG);
        const int rowA = wid * 16;
#pragma unroll
        for (int ks = 0; ks < 2; ks++) {
            const int kb = ks * 16;
            uint32_t afr[4];
            ldsm4(afr, smA + (uint32_t)(rowA * PB + kb + aoff) * 2);
            uint32_t bfr[4][2];
#pragma unroll
            for (int np = 0; np < 2; np++) {
                uint32_t rr[4];
                ldsm4(rr, smW + (uint32_t)((np * 16) * WP + k0 + kb + boffW) * 2);
                bfr[2 * np][0] = rr[0]; bfr[2 * np][1] = rr[1];
                bfr[2 * np + 1][0] = rr[2]; bfr[2 * np + 1][1] = rr[3];
            }
#pragma unroll
            for (int nt = 0; nt < 4; nt++)
                mma_bf16(acc[nt], afr, bfr[nt]);
        }
        __syncthreads();
    }

    // stage gates to smem (f32, pitch SMPF) — reuse A-stage smem
    float* Ss = (float*)Asm;
#pragma unroll
    for (int nt = 0; nt < 4; nt++) {
#pragma unroll
        for (int r = 0; r < 4; r++) {
            int row = wid * 16 + g + ((r & 2) ? 8 : 0);
            int col = nt * 8 + 2 * t4 + (r & 1);
            Ss[row * SMPF + col] = acc[nt][r];
        }
    }
    __syncthreads();

    // fused LSTM pointwise: 64 rows x 8 j-cols (f32 state)
#pragma unroll
    for (int it = 0; it < 4; it++) {
        int idx = it * 128 + tid;
        int rl = idx >> 3, jj = idx & 7;
        int row = rb + rl;
        int j = j0 + jj;
        float gi = Ss[rl * SMPF + jj];
        float gf = Ss[rl * SMPF + 8 + jj];
        float gg = Ss[rl * SMPF + 16 + jj];
        float go = Ss[rl * SMPF + 24 + jj];
        if (xpre) {
            const float* xp = xpre + (size_t)row * G4 + j;
            gi += xp[0]; gf += xp[512]; gg += xp[1024]; go += xp[1536];
        }
        if (bias) {
            gi += bias[j]; gf += bias[512 + j];
            gg += bias[1024 + j]; go += bias[1536 + j];
        }
        float cv = c[row * 512 + j];
        float cn = sigmoidf_(gf) * cv + sigmoidf_(gi) * tanhf(gg);
        c[row * 512 + j] = cn;
        float h = sigmoidf_(go) * tanhf(cn);
        __nv_bfloat16 hb = __float2bfloat16(h);
        stcg_bf16(&hout[(size_t)row * 1024 + hoff + j], hb);
        if (hcopy) hcopy[row * 512 + j] = hb;
    }
}

// =====================================================================
// cell1_persist: all 109 cell1 phases; W1 slice resident in smem.
// 128 CTAs x 128 thr. Waits: cnt1[t-1] (RAW h1), cnt2[t-4] (WAR buffer).
// =====================================================================
__global__ __launch_bounds__(128, 1) void cell1_persist() {
    extern __shared__ __nv_bfloat16 sm1[];
    __nv_bfloat16* Wsm = sm1;                // [32][WP1]
    __nv_bfloat16* Asm = sm1 + 32 * WP1;     // [4][ASTG]
    const int tid = threadIdx.x;
    const int j0 = (blockIdx.x >> 1) * 8;
    const int rb = (blockIdx.x & 1) * 64;

    for (int idx = tid; idx < 32 * 64; idx += 128) {
        int lc = idx >> 6, seg = (idx & 63) * 8;
        int n = (lc >> 3) * 512 + j0 + (lc & 7);
        cp16(Wsm + lc * WP1 + seg, g_whh1b + (size_t)n * 512 + seg, true);
    }
    CP_COMMIT(); CP_WAIT0(); __syncthreads();

    for (int t = 0; t < NSTEP; t++) {
        if (t > 0) wait_cnt(&g_cnt1[t - 1]);
        if (t >= 4) wait_cnt(&g_cnt2[t - 4]);
        const __nv_bfloat16* bPrev = g_h12b + (size_t)((t + 3) & 3) * BU;
        __nv_bfloat16* bCur = g_h12b + (size_t)(t & 3) * BU;
        bool enc = t < TFRM;
        cell_step<512, WP1>(bPrev, bPrev, Wsm, Asm,
                            enc ? (g_X1pre + (size_t)t * BATCH * G4) : nullptr,
                            enc ? nullptr : g_bias1,
                            g_c1, bCur, 0, nullptr, j0, rb);
        __syncthreads();
        if (tid == 0) red_rel(&g_cnt1[t]);
    }
}

// =====================================================================
// cell2_persist: all 109 cell2 phases; W2cat slice resident in smem.
// Waits: cnt1[t] (RAW h1(t)), cnt2[t-1] (RAW h2(t-1)).
// =====================================================================
__global__ __launch_bounds__(128, 1) void cell2_persist() {
    extern __shared__ __nv_bfloat16 sm2[];
    __nv_bfloat16* Wsm = sm2;                // [32][WP2]
    __nv_bfloat16* Asm = sm2 + 32 * WP2;     // [4][ASTG]
    const int tid = threadIdx.x;
    const int j0 = (blockIdx.x >> 1) * 8;
    const int rb = (blockIdx.x & 1) * 64;

    for (int idx = tid; idx < 32 * 128; idx += 128) {
        int lc = idx >> 7, seg = (idx & 127) * 8;
        int n = (lc >> 3) * 512 + j0 + (lc & 7);
        cp16(Wsm + lc * WP2 + seg, g_W2catb + (size_t)n * 1024 + seg, true);
    }
    CP_COMMIT(); CP_WAIT0(); __syncthreads();

    for (int t = 0; t < NSTEP; t++) {
        if (t > 0) wait_cnt(&g_cnt2[t - 1]);
        wait_cnt(&g_cnt1[t]);
        const __nv_bfloat16* bPrev = g_h12b + (size_t)((t + 3) & 3) * BU;
        __nv_bfloat16* bCur = g_h12b + (size_t)(t & 3) * BU;
        bool enc = t < TFRM;
        int s = t - TFRM;
        cell_step<1024, WP2>(bCur, bPrev, Wsm, Asm,
                             enc ? nullptr : (g_Wx2 + (size_t)s * BATCH * G4),
                             g_bias2,
                             g_c2, bCur, 512,
                             enc ? nullptr : (g_H2b + (size_t)s * BATCH * EDIM),
                             j0, rb);
        __syncthreads();
        if (tid == 0) red_rel(&g_cnt2[t]);
    }
}

// ---------------- argmax over vocab ----------------
__global__ void argmax_kernel(const float* __restrict__ oh) {
    int r = blockIdx.x;
    int s = r >> 7, b = r & 127;
    const float* row = oh + (size_t)b * (DECL * VOC) + (size_t)(s + 1) * VOC;
    __shared__ float sv[128];
    __shared__ int si[128];
    int tid = threadIdx.x;
    float best = -3.4e38f; int bi = 0;
    for (int i = tid; i < VOC; i += 128) {
        float v = row[i];
        if (v > best) { best = v; bi = i; }
    }
    sv[tid] = best; si[tid] = bi;
    __syncthreads();
    for (int o = 64; o > 0; o >>= 1) {
        if (tid < o) {
            if (sv[tid + o] > sv[tid] || (sv[tid + o] == sv[tid] && si[tid + o] < si[tid])) {
                sv[tid] = sv[tid + o]; si[tid] = si[tid + o];
            }
        }
        __syncthreads();
    }
    if (tid == 0) g_labels[r] = si[0];
}

// ---------------- per-row NLL ----------------
__global__ void loss_kernel() {
    int r = blockIdx.x;
    const float* row = g_logits + (size_t)r * VOC;
    __shared__ float red[256];
    int tid = threadIdx.x;
    float m = -3.4e38f;
    for (int i = tid; i < VOC; i += 256) m = fmaxf(m, row[i]);
    red[tid] = m; __syncthreads();
    for (int o = 128; o > 0; o >>= 1) {
        if (tid < o) red[tid] = fmaxf(red[tid], red[tid + o]);
        __syncthreads();
    }
    float mall = red[0];
    __syncthreads();
    float sacc = 0.f;
    for (int i = tid; i < VOC; i += 256) sacc += expf(row[i] - mall);
    red[tid] = sacc; __syncthreads();
    for (int o = 128; o > 0; o >>= 1) {
        if (tid < o) red[tid] += red[tid + o];
        __syncthreads();
    }
    if (tid == 0) {
        int lab = g_labels[r];
        g_rowloss[r] = (mall + logf(red[0])) - row[lab];
    }
}

__global__ void final_reduce(float* out) {
    __shared__ float red[256];
    int tid = threadIdx.x;
    float s = 0.f;
    for (int i = tid; i < DSTEPS * BATCH; i += 256) s += g_rowloss[i];
    red[tid] = s; __syncthreads();
    for (int o = 128; o > 0; o >>= 1) {
        if (tid < o) red[tid] += red[tid + o];
        __syncthreads();
    }
    if (tid == 0) out[0] = red[0] * (1.0f / 128.0f);
}

// ---------------- host ----------------
extern "C" void kernel_launch(void* const* d_in, const int* in_sizes, int n_in,
                              void* d_out, int out_size) {
    const float* feat    = (const float*)d_in[0];
    const float* caption = (const float*)d_in[1];
    const float* oh      = (const float*)d_in[2];
    const float* w_ih1   = (const float*)d_in[3];
    const float* w_hh1   = (const float*)d_in[4];
    const float* b_ih1   = (const float*)d_in[5];
    const float* b_hh1   = (const float*)d_in[6];
    const float* w_ih2   = (const float*)d_in[7];
    const float* w_hh2   = (const float*)d_in[8];
    const float* b_ih2   = (const float*)d_in[9];
    const float* b_hh2   = (const float*)d_in[10];
    const float* w_out   = (const float*)d_in[11];
    const float* b_out   = (const float*)d_in[12];
    float* out = (float*)d_out;

    float *pX1, *pWx2, *pB1, *pLog;
    __nv_bfloat16 *pFb, *pCb, *pW1b, *pW2b, *pWOb, *pH2b;
    cudaGetSymbolAddress((void**)&pX1,  g_X1pre);
    cudaGetSymbolAddress((void**)&pWx2, g_Wx2);
    cudaGetSymbolAddress((void**)&pB1,  g_bias1);
    cudaGetSymbolAddress((void**)&pLog, g_logits);
    cudaGetSymbolAddress((void**)&pFb,  g_featb);
    cudaGetSymbolAddress((void**)&pCb,  g_capb);
    cudaGetSymbolAddress((void**)&pW1b, g_wih1b);
    cudaGetSymbolAddress((void**)&pW2b, g_wih2b);
    cudaGetSymbolAddress((void**)&pWOb, g_woutb);
    cudaGetSymbolAddress((void**)&pH2b, g_H2b);

    static bool init_done = false;
    static cudaStream_t s1, s2;
    static cudaEvent_t evStart, evD1, evD2;
    if (!init_done) {
        cudaFuncSetAttribute(bf16_gemm256,
                             cudaFuncAttributeMaxDynamicSharedMemorySize, BGEMM_SMEM);
        cudaFuncSetAttribute(cell1_persist,
                             cudaFuncAttributeMaxDynamicSharedMemorySize, C1_SMEM);
        cudaFuncSetAttribute(cell2_persist,
                             cudaFuncAttributeMaxDynamicSharedMemorySize, C2_SMEM);
        cudaStreamCreateWithFlags(&s1, cudaStreamNonBlocking);
        cudaStreamCreateWithFlags(&s2, cudaStreamNonBlocking);
        cudaEventCreateWithFlags(&evStart, cudaEventDisableTiming);
        cudaEventCreateWithFlags(&evD1, cudaEventDisableTiming);
        cudaEventCreateWithFlags(&evD2, cudaEventDisableTiming);
        init_done = true;
    }

    // ---- serial prefix on stream 0 (R14 structure — no recurrence contention) ----
    init_kernel<<<1536, 256>>>(b_ih1, b_hh1, b_ih2, b_hh2, out);
    w2cat_kernel<<<8192, 256>>>(w_ih2, w_hh2);
    {
        int nf = BATCH * TFRM * FEATD;
        cvt_bf16<<<nf / 1024, 256>>>(feat, pFb, nf);
        int nw = G4 * FEATD;
        cvt_bf16<<<nw / 1024, 256>>>(w_ih1, pW1b, nw);
        cvt_bf16<<<(G4 * EDIM) / 1024, 256>>>(w_hh1, (__nv_bfloat16*)nullptr + 0, 0);  // placeholder removed below
    }
    // (re-issue correctly: w_hh1 -> g_whh1b)
    {
        __nv_bfloat16* pWhh1b;
        cudaGetSymbolAddress((void**)&pWhh1b, g_whh1b);
        cvt_bf16<<<(G4 * EDIM) / 1024, 256>>>(w_hh1, pWhh1b, G4 * EDIM);
        int nc = BATCH * DECL * EDIM;
        cvt_bf16<<<nc / 1024, 256>>>(caption, pCb, nc);
        cvt_wih2<<<(G4 * EDIM) / 1024, 256>>>(w_ih2, pW2b);
    }

    // X1pre = feat @ w_ih1^T + bias1   [10240 x 2048]
    bf16_gemm256<<<dim3(8, 80), 256, BGEMM_SMEM>>>(
        pFb, (size_t)FEATD, (size_t)TFRM * FEATD, pW1b, FEATD, pB1, pX1, G4, FEATD);
    // Wx2 = caption @ w_ih2[:, :512]^T
    bf16_gemm256<<<dim3(8, 29), 256, BGEMM_SMEM>>>(
        pCb, (size_t)EDIM, (size_t)DECL * EDIM, pW2b, EDIM, nullptr, pWx2, G4, EDIM);

    cudaEventRecord(evStart, 0);
    cudaStreamWaitEvent(s1, evStart, 0);
    cudaStreamWaitEvent(s2, evStart, 0);

    // ---- recurrence: two persistent chains, L2 flag sync ----
    cell1_persist<<<128, 128, C1_SMEM, s1>>>();
    cudaEventRecord(evD1, s1);
    cell2_persist<<<128, 128, C2_SMEM, s2>>>();
    cudaEventRecord(evD2, s2);

    // ---- stream 0: tail prep (uses leftover SM slots during recurrence) ----
    cvt_bf16<<<(VOC * EDIM) / 1024, 256>>>(w_out, pWOb, VOC * EDIM);
    argmax_kernel<<<DSTEPS * BATCH, 128>>>(oh);

    cudaStreamWaitEvent(0, evD1, 0);
    cudaStreamWaitEvent(0, evD2, 0);

    // logits = H2b @ w_out^T + b_out   [3712 x 6000]
    bf16_gemm256<<<dim3(24, 29), 256, BGEMM_SMEM>>>(
        pH2b, (size_t)BATCH * EDIM, (size_t)EDIM, pWOb, EDIM, b_out, pLog, VOC, EDIM);
    loss_kernel<<<DSTEPS * BATCH, 256>>>();
    final_reduce<<<1, 256>>>(out);
}